// round 10
// baseline (speedup 1.0000x reference)
#include <cuda_runtime.h>
#include <cuda_bf16.h>
#include <cstdint>

#define NN 50000
#define NE 1600000
#define DIM 128
#define DOUT 64
#define NB_SCAN 49   // ceil(50000/1024)
#define APITCH 40    // bf16 pitch: 80B rows -> ldmatrix bank-conflict-free

// ---------------- scratch (device globals; no allocations allowed) ----------
__device__ int   g_is32;                     // 1 if edge_index is int32
__device__ int   g_deg[NN];
__device__ int   g_off[NN];
__device__ int   g_cur[NN];
__device__ int   g_bsum[64];
__device__ int   g_csr[NE];
// bf16 hi/lo planes (split-precision operands)
__device__ __align__(16) __nv_bfloat16 g_xh[(size_t)NN * DIM];
__device__ __align__(16) __nv_bfloat16 g_xl[(size_t)NN * DIM];
__device__ __align__(16) __nv_bfloat16 g_a1h[(size_t)NN * DIM];
__device__ __align__(16) __nv_bfloat16 g_a1l[(size_t)NN * DIM];
__device__ __align__(16) __nv_bfloat16 g_hh[(size_t)NN * DIM];
__device__ __align__(16) __nv_bfloat16 g_hl[(size_t)NN * DIM];
__device__ __align__(16) __nv_bfloat16 g_w1h[256 * 128];   // [n=128][k=256] transposed
__device__ __align__(16) __nv_bfloat16 g_w1l[256 * 128];
__device__ __align__(16) __nv_bfloat16 g_w2h[128 * 128];   // [n=128][k=128] transposed
__device__ __align__(16) __nv_bfloat16 g_w2l[128 * 128];
__device__ __align__(16) float g_pr[(size_t)NN * DIM];     // [h@W2l | h@W2r] fp32

// ---------------- mma / ldmatrix helpers ------------------------------------
__device__ __forceinline__ void mma16816(float* d, const unsigned* a,
                                         unsigned b0, unsigned b1) {
    asm("mma.sync.aligned.m16n8k16.row.col.f32.bf16.bf16.f32 "
        "{%0,%1,%2,%3}, {%4,%5,%6,%7}, {%8,%9}, {%0,%1,%2,%3};"
        : "+f"(d[0]), "+f"(d[1]), "+f"(d[2]), "+f"(d[3])
        : "r"(a[0]), "r"(a[1]), "r"(a[2]), "r"(a[3]), "r"(b0), "r"(b1));
}

__device__ __forceinline__ void ldm_x4(unsigned* r, const __nv_bfloat16* p) {
    unsigned addr = (unsigned)__cvta_generic_to_shared(p);
    asm volatile("ldmatrix.sync.aligned.m8n8.x4.shared.b16 {%0,%1,%2,%3}, [%4];"
                 : "=r"(r[0]), "=r"(r[1]), "=r"(r[2]), "=r"(r[3]) : "r"(addr));
}

__device__ __forceinline__ void split2(float f, __nv_bfloat16& h, __nv_bfloat16& l) {
    h = __float2bfloat16_rn(f);
    l = __float2bfloat16_rn(f - __bfloat162float(h));
}

// ---------------- one-time operand conversion --------------------------------
__global__ void k_cvtx(const float* __restrict__ x) {
    int i = blockIdx.x * blockDim.x + threadIdx.x;   // float4 index
    if (i >= NN * 32) return;
    float4 v = ((const float4*)x)[i];
    __nv_bfloat16 h0, l0, h1, l1, h2, l2, h3, l3;
    split2(v.x, h0, l0); split2(v.y, h1, l1);
    split2(v.z, h2, l2); split2(v.w, h3, l3);
    ((__nv_bfloat162*)g_xh)[i * 2]     = __nv_bfloat162{h0, h1};
    ((__nv_bfloat162*)g_xh)[i * 2 + 1] = __nv_bfloat162{h2, h3};
    ((__nv_bfloat162*)g_xl)[i * 2]     = __nv_bfloat162{l0, l1};
    ((__nv_bfloat162*)g_xl)[i * 2 + 1] = __nv_bfloat162{l2, l3};
}

// weights -> transposed hi/lo planes: g_w1 [n=128][k=256], g_w2 [n=128][k=128]
__global__ void k_cvtw(const float* __restrict__ W1l, const float* __restrict__ W1r,
                       const float* __restrict__ W2l, const float* __restrict__ W2r) {
    int i = blockIdx.x * blockDim.x + threadIdx.x;
    if (i < 128 * 256) {                 // W1: i = n*256 + k
        int n = i >> 8, k = i & 255;
        float v = (k < 128) ? W1l[(size_t)k * 128 + n]
                            : W1r[(size_t)(k - 128) * 128 + n];
        split2(v, g_w1h[i], g_w1l[i]);
    } else if (i < 128 * 256 + 128 * 128) {
        int j = i - 128 * 256;           // W2: j = n*128 + k
        int n = j >> 7, k = j & 127;
        float v = (n < 64) ? W2l[(size_t)k * 64 + n]
                           : W2r[(size_t)k * 64 + (n - 64)];
        split2(v, g_w2h[j], g_w2l[j]);
    }
}

// ---------------- dtype detection -------------------------------------------
__global__ void k_detect(const unsigned* __restrict__ w) {
    if (threadIdx.x == 0) g_is32 = 0;
    __syncthreads();
    int found = 0;
    for (int i = threadIdx.x; i < 1024; i += blockDim.x)
        if (w[2 * i + 1] != 0u) found = 1;
    if (found) atomicOr(&g_is32, 1);
}

// ---------------- CSR construction ------------------------------------------
__global__ void k_zero() {
    int i = blockIdx.x * blockDim.x + threadIdx.x;
    if (i < NN) g_deg[i] = 0;
}

__global__ void k_deg(const int* __restrict__ e32,
                      const long long* __restrict__ e64) {
    int base = (blockIdx.x * blockDim.x + threadIdx.x) * 4;
    if (base >= NE) return;
    int d0, d1, d2, d3;
    if (g_is32) {
        int4 v = *(const int4*)(e32 + NE + base);
        d0 = v.x; d1 = v.y; d2 = v.z; d3 = v.w;
    } else {
        longlong2 v0 = *(const longlong2*)(e64 + NE + base);
        longlong2 v1 = *(const longlong2*)(e64 + NE + base + 2);
        d0 = (int)v0.x; d1 = (int)v0.y; d2 = (int)v1.x; d3 = (int)v1.y;
    }
    if ((unsigned)d0 < NN) atomicAdd(&g_deg[d0], 1);
    if ((unsigned)d1 < NN) atomicAdd(&g_deg[d1], 1);
    if ((unsigned)d2 < NN) atomicAdd(&g_deg[d2], 1);
    if ((unsigned)d3 < NN) atomicAdd(&g_deg[d3], 1);
}

__global__ void k_scanA() {
    __shared__ int wsum[32];
    int i = blockIdx.x * 1024 + threadIdx.x;
    int v = (i < NN) ? g_deg[i] : 0;
    int lane = threadIdx.x & 31, wid = threadIdx.x >> 5;
    int s = v;
#pragma unroll
    for (int o = 1; o < 32; o <<= 1) {
        int t = __shfl_up_sync(0xffffffffu, s, o);
        if (lane >= o) s += t;
    }
    if (lane == 31) wsum[wid] = s;
    __syncthreads();
    if (wid == 0) {
        int ws = wsum[lane];
#pragma unroll
        for (int o = 1; o < 32; o <<= 1) {
            int t = __shfl_up_sync(0xffffffffu, ws, o);
            if (lane >= o) ws += t;
        }
        wsum[lane] = ws;
    }
    __syncthreads();
    int base = wid ? wsum[wid - 1] : 0;
    if (i < NN) g_off[i] = base + s - v;
    if (threadIdx.x == 0) g_bsum[blockIdx.x] = wsum[31];
}

__global__ void k_scanB() {
    if (threadIdx.x == 0 && blockIdx.x == 0) {
        int acc = 0;
        for (int b = 0; b < NB_SCAN; b++) { int t = g_bsum[b]; g_bsum[b] = acc; acc += t; }
    }
}

__global__ void k_scanC() {
    int i = blockIdx.x * 1024 + threadIdx.x;
    if (i < NN) {
        int o = g_off[i] + g_bsum[blockIdx.x];
        g_off[i] = o;
        g_cur[i] = o;
    }
}

__global__ void k_scatter(const int* __restrict__ e32,
                          const long long* __restrict__ e64) {
    int base = (blockIdx.x * blockDim.x + threadIdx.x) * 4;
    if (base >= NE) return;
    int s0, s1, s2, s3, d0, d1, d2, d3;
    if (g_is32) {
        int4 sv = *(const int4*)(e32 + base);
        int4 dv = *(const int4*)(e32 + NE + base);
        s0 = sv.x; s1 = sv.y; s2 = sv.z; s3 = sv.w;
        d0 = dv.x; d1 = dv.y; d2 = dv.z; d3 = dv.w;
    } else {
        longlong2 sa = *(const longlong2*)(e64 + base);
        longlong2 sb = *(const longlong2*)(e64 + base + 2);
        longlong2 da = *(const longlong2*)(e64 + NE + base);
        longlong2 db = *(const longlong2*)(e64 + NE + base + 2);
        s0 = (int)sa.x; s1 = (int)sa.y; s2 = (int)sb.x; s3 = (int)sb.y;
        d0 = (int)da.x; d1 = (int)da.y; d2 = (int)db.x; d3 = (int)db.y;
    }
    if ((unsigned)d0 < NN) g_csr[atomicAdd(&g_cur[d0], 1)] = ((unsigned)s0 < NN) ? s0 : 0;
    if ((unsigned)d1 < NN) g_csr[atomicAdd(&g_cur[d1], 1)] = ((unsigned)s1 < NN) ? s1 : 0;
    if ((unsigned)d2 < NN) g_csr[atomicAdd(&g_cur[d2], 1)] = ((unsigned)s2 < NN) ? s2 : 0;
    if ((unsigned)d3 < NN) g_csr[atomicAdd(&g_cur[d3], 1)] = ((unsigned)s3 < NN) ? s3 : 0;
}

// ---------------- aggregation (warp per node, CSR gather) -------------------
// mean-aggregate x -> hi/lo bf16 planes g_a1h/g_a1l
__global__ void k_agg128(const float* __restrict__ src) {
    int w = (blockIdx.x * blockDim.x + threadIdx.x) >> 5;
    if (w >= NN) return;
    int lane = threadIdx.x & 31;
    int start = g_off[w];
    int d = g_deg[w];
    const float4* sv = (const float4*)src;
    float4 a0 = make_float4(0.f, 0.f, 0.f, 0.f);
    float4 a1 = make_float4(0.f, 0.f, 0.f, 0.f);
    for (int j = 0; j < d; j += 32) {
        int m = min(32, d - j);
        int sidx = (j + lane < d) ? g_csr[start + j + lane] : 0;
        int jj = 0;
        for (; jj + 2 <= m; jj += 2) {
            int s0 = __shfl_sync(0xffffffffu, sidx, jj);
            int s1 = __shfl_sync(0xffffffffu, sidx, jj + 1);
            float4 v0 = sv[(size_t)s0 * 32 + lane];
            float4 v1 = sv[(size_t)s1 * 32 + lane];
            a0.x += v0.x; a0.y += v0.y; a0.z += v0.z; a0.w += v0.w;
            a1.x += v1.x; a1.y += v1.y; a1.z += v1.z; a1.w += v1.w;
        }
        if (jj < m) {
            int s0 = __shfl_sync(0xffffffffu, sidx, jj);
            float4 v0 = sv[(size_t)s0 * 32 + lane];
            a0.x += v0.x; a0.y += v0.y; a0.z += v0.z; a0.w += v0.w;
        }
    }
    float inv = 1.0f / (float)max(d, 1);
    float r0 = (a0.x + a1.x) * inv;
    float r1 = (a0.y + a1.y) * inv;
    float r2 = (a0.z + a1.z) * inv;
    float r3 = (a0.w + a1.w) * inv;
    __nv_bfloat16 h0, l0, h1, l1, h2, l2, h3, l3;
    split2(r0, h0, l0); split2(r1, h1, l1);
    split2(r2, h2, l2); split2(r3, h3, l3);
    size_t p = (size_t)w * 64 + lane * 2;        // __nv_bfloat162 index
    ((__nv_bfloat162*)g_a1h)[p]     = __nv_bfloat162{h0, h1};
    ((__nv_bfloat162*)g_a1h)[p + 1] = __nv_bfloat162{h2, h3};
    ((__nv_bfloat162*)g_a1l)[p]     = __nv_bfloat162{l0, l1};
    ((__nv_bfloat162*)g_a1l)[p + 1] = __nv_bfloat162{l2, l3};
}

// aggregate first 64 cols of g_pr (h@W2_l) + self term + bias -> out
__global__ void k_agg64f(const float* __restrict__ b2, float* __restrict__ out) {
    int w = (blockIdx.x * blockDim.x + threadIdx.x) >> 5;
    if (w >= NN) return;
    int lane = threadIdx.x & 31;
    int start = g_off[w];
    int d = g_deg[w];
    const float2* sv = (const float2*)g_pr;
    float2 a0 = make_float2(0.f, 0.f);
    float2 a1 = make_float2(0.f, 0.f);
    for (int j = 0; j < d; j += 32) {
        int m = min(32, d - j);
        int sidx = (j + lane < d) ? g_csr[start + j + lane] : 0;
        int jj = 0;
        for (; jj + 2 <= m; jj += 2) {
            int s0 = __shfl_sync(0xffffffffu, sidx, jj);
            int s1 = __shfl_sync(0xffffffffu, sidx, jj + 1);
            float2 v0 = sv[(size_t)s0 * 64 + lane];
            float2 v1 = sv[(size_t)s1 * 64 + lane];
            a0.x += v0.x; a0.y += v0.y;
            a1.x += v1.x; a1.y += v1.y;
        }
        if (jj < m) {
            int s0 = __shfl_sync(0xffffffffu, sidx, jj);
            float2 v0 = sv[(size_t)s0 * 64 + lane];
            a0.x += v0.x; a0.y += v0.y;
        }
    }
    float inv = 1.0f / (float)max(d, 1);
    float2 selfr = sv[(size_t)w * 64 + 32 + lane];
    float2 bb = ((const float2*)b2)[lane];
    float2 o;
    o.x = (a0.x + a1.x) * inv + selfr.x + bb.x;
    o.y = (a0.y + a1.y) * inv + selfr.y + bb.y;
    ((float2*)out)[(size_t)w * 32 + lane] = o;
}

// ---------------- GEMM 1 (bf16x3 TC, preconverted operands) ------------------
// h(hi/lo) = relu([agg1|x] @ [W1_l;W1_r] + b1); M=NN, N=128, K=256.
__global__ __launch_bounds__(256) void k_gemm1(const float* __restrict__ bias) {
    __shared__ __nv_bfloat16 Ah[128][APITCH], Al[128][APITCH];
    __shared__ __nv_bfloat16 Bh[128][APITCH], Bl[128][APITCH];  // BT: [n][k]
    const int tid = threadIdx.x, lane = tid & 31, wid = tid >> 5;
    const int wm = (wid & 1) * 64, wn = (wid >> 1) * 32;
    const int bm = blockIdx.x * 128;
    float acc[4][4][4];
#pragma unroll
    for (int mt = 0; mt < 4; mt++)
#pragma unroll
        for (int nt = 0; nt < 4; nt++)
#pragma unroll
            for (int q = 0; q < 4; q++) acc[mt][nt][q] = 0.f;

    for (int kc = 0; kc < 256; kc += 32) {
        // stage A: 128 rows x 32 k, hi/lo bf16 copies (8 bf16 per uint4)
#pragma unroll
        for (int i = 0; i < 2; i++) {
            int f = tid + 256 * i;            // 0..511
            int r = f >> 2, c8 = (f & 3) * 8;
            int row = bm + r, k = kc + c8;
            uint4 vh = make_uint4(0, 0, 0, 0), vl = make_uint4(0, 0, 0, 0);
            if (row < NN) {
                size_t idx = (k < 128) ? ((size_t)row * 128 + k)
                                       : ((size_t)row * 128 + (k - 128));
                const __nv_bfloat16* ph = (k < 128) ? g_a1h : g_xh;
                const __nv_bfloat16* pl = (k < 128) ? g_a1l : g_xl;
                vh = *(const uint4*)(ph + idx);
                vl = *(const uint4*)(pl + idx);
            }
            *(uint4*)&Ah[r][c8] = vh;
            *(uint4*)&Al[r][c8] = vl;
        }
        // stage B: [n][k] planes, straight copy
#pragma unroll
        for (int i = 0; i < 2; i++) {
            int f = tid + 256 * i;
            int n = f >> 2, c8 = (f & 3) * 8;
            *(uint4*)&Bh[n][c8] = *(const uint4*)(g_w1h + (size_t)n * 256 + kc + c8);
            *(uint4*)&Bl[n][c8] = *(const uint4*)(g_w1l + (size_t)n * 256 + kc + c8);
        }
        __syncthreads();
#pragma unroll
        for (int k16 = 0; k16 < 32; k16 += 16) {
            unsigned ah[4][4], al[4][4];
            int arow = wm + (lane & 15);
            int acol = k16 + ((lane >> 4) << 3);
#pragma unroll
            for (int mt = 0; mt < 4; mt++) {
                ldm_x4(ah[mt], &Ah[arow + mt * 16][acol]);
                ldm_x4(al[mt], &Al[arow + mt * 16][acol]);
            }
#pragma unroll
            for (int nt = 0; nt < 4; nt++) {
                int bn = wn + nt * 8 + (lane >> 2);
                int bk = k16 + 2 * (lane & 3);
                unsigned bh0 = *(const unsigned*)&Bh[bn][bk];
                unsigned bh1 = *(const unsigned*)&Bh[bn][bk + 8];
                unsigned bl0 = *(const unsigned*)&Bl[bn][bk];
                unsigned bl1 = *(const unsigned*)&Bl[bn][bk + 8];
#pragma unroll
                for (int mt = 0; mt < 4; mt++) {
                    mma16816(acc[mt][nt], ah[mt], bh0, bh1);
                    mma16816(acc[mt][nt], ah[mt], bl0, bl1);
                    mma16816(acc[mt][nt], al[mt], bh0, bh1);
                }
            }
        }
        __syncthreads();
    }
    // epilogue: bias + relu -> hi/lo planes
#pragma unroll
    for (int mt = 0; mt < 4; mt++) {
#pragma unroll
        for (int nt = 0; nt < 4; nt++) {
            int col = wn + nt * 8 + 2 * (lane & 3);
            float bv0 = bias[col], bv1 = bias[col + 1];
            int row0 = bm + wm + mt * 16 + (lane >> 2);
            if (row0 < NN) {
                float o0 = fmaxf(acc[mt][nt][0] + bv0, 0.f);
                float o1 = fmaxf(acc[mt][nt][1] + bv1, 0.f);
                __nv_bfloat16 h0, l0, h1, l1;
                split2(o0, h0, l0); split2(o1, h1, l1);
                *(__nv_bfloat162*)&g_hh[(size_t)row0 * 128 + col] = __nv_bfloat162{h0, h1};
                *(__nv_bfloat162*)&g_hl[(size_t)row0 * 128 + col] = __nv_bfloat162{l0, l1};
            }
            int row1 = row0 + 8;
            if (row1 < NN) {
                float o0 = fmaxf(acc[mt][nt][2] + bv0, 0.f);
                float o1 = fmaxf(acc[mt][nt][3] + bv1, 0.f);
                __nv_bfloat16 h0, l0, h1, l1;
                split2(o0, h0, l0); split2(o1, h1, l1);
                *(__nv_bfloat162*)&g_hh[(size_t)row1 * 128 + col] = __nv_bfloat162{h0, h1};
                *(__nv_bfloat162*)&g_hl[(size_t)row1 * 128 + col] = __nv_bfloat162{l0, l1};
            }
        }
    }
}

// ---------------- GEMM 2 (bf16x3 TC, preconverted operands) ------------------
// g_pr = h @ [W2_l | W2_r]; M=NN, N=128, K=128.
__global__ __launch_bounds__(256) void k_gemm2() {
    __shared__ __nv_bfloat16 Ah[128][APITCH], Al[128][APITCH];
    __shared__ __nv_bfloat16 Bh[128][APITCH], Bl[128][APITCH];
    const int tid = threadIdx.x, lane = tid & 31, wid = tid >> 5;
    const int wm = (wid & 1) * 64, wn = (wid >> 1) * 32;
    const int bm = blockIdx.x * 128;
    float acc[4][4][4];
#pragma unroll
    for (int mt = 0; mt < 4; mt++)
#pragma unroll
        for (int nt = 0; nt < 4; nt++)
#pragma unroll
            for (int q = 0; q < 4; q++) acc[mt][nt][q] = 0.f;

    for (int kc = 0; kc < 128; kc += 32) {
#pragma unroll
        for (int i = 0; i < 2; i++) {
            int f = tid + 256 * i;
            int r = f >> 2, c8 = (f & 3) * 8;
            int row = bm + r, k = kc + c8;
            uint4 vh = make_uint4(0, 0, 0, 0), vl = make_uint4(0, 0, 0, 0);
            if (row < NN) {
                vh = *(const uint4*)(g_hh + (size_t)row * 128 + k);
                vl = *(const uint4*)(g_hl + (size_t)row * 128 + k);
            }
            *(uint4*)&Ah[r][c8] = vh;
            *(uint4*)&Al[r][c8] = vl;
        }
#pragma unroll
        for (int i = 0; i < 2; i++) {
            int f = tid + 256 * i;
            int n = f >> 2, c8 = (f & 3) * 8;
            *(uint4*)&Bh[n][c8] = *(const uint4*)(g_w2h + (size_t)n * 128 + kc + c8);
            *(uint4*)&Bl[n][c8] = *(const uint4*)(g_w2l + (size_t)n * 128 + kc + c8);
        }
        __syncthreads();
#pragma unroll
        for (int k16 = 0; k16 < 32; k16 += 16) {
            unsigned ah[4][4], al[4][4];
            int arow = wm + (lane & 15);
            int acol = k16 + ((lane >> 4) << 3);
#pragma unroll
            for (int mt = 0; mt < 4; mt++) {
                ldm_x4(ah[mt], &Ah[arow + mt * 16][acol]);
                ldm_x4(al[mt], &Al[arow + mt * 16][acol]);
            }
#pragma unroll
            for (int nt = 0; nt < 4; nt++) {
                int bn = wn + nt * 8 + (lane >> 2);
                int bk = k16 + 2 * (lane & 3);
                unsigned bh0 = *(const unsigned*)&Bh[bn][bk];
                unsigned bh1 = *(const unsigned*)&Bh[bn][bk + 8];
                unsigned bl0 = *(const unsigned*)&Bl[bn][bk];
                unsigned bl1 = *(const unsigned*)&Bl[bn][bk + 8];
#pragma unroll
                for (int mt = 0; mt < 4; mt++) {
                    mma16816(acc[mt][nt], ah[mt], bh0, bh1);
                    mma16816(acc[mt][nt], ah[mt], bl0, bl1);
                    mma16816(acc[mt][nt], al[mt], bh0, bh1);
                }
            }
        }
        __syncthreads();
    }
#pragma unroll
    for (int mt = 0; mt < 4; mt++) {
#pragma unroll
        for (int nt = 0; nt < 4; nt++) {
            int col = wn + nt * 8 + 2 * (lane & 3);
            int row0 = bm + wm + mt * 16 + (lane >> 2);
            if (row0 < NN) {
                float2 o = make_float2(acc[mt][nt][0], acc[mt][nt][1]);
                *(float2*)&g_pr[(size_t)row0 * 128 + col] = o;
            }
            int row1 = row0 + 8;
            if (row1 < NN) {
                float2 o = make_float2(acc[mt][nt][2], acc[mt][nt][3]);
                *(float2*)&g_pr[(size_t)row1 * 128 + col] = o;
            }
        }
    }
}

// ---------------- launch ----------------------------------------------------
extern "C" void kernel_launch(void* const* d_in, const int* in_sizes, int n_in,
                              void* d_out, int out_size) {
    const float*     x   = (const float*)d_in[0];
    const int*       e32 = (const int*)d_in[1];
    const long long* e64 = (const long long*)d_in[1];
    const unsigned*  ew  = (const unsigned*)d_in[1];
    const float*     W1l = (const float*)d_in[2];
    const float*     W1r = (const float*)d_in[3];
    const float*     b1  = (const float*)d_in[4];
    const float*     W2l = (const float*)d_in[5];
    const float*     W2r = (const float*)d_in[6];
    const float*     b2  = (const float*)d_in[7];
    float*           out = (float*)d_out;

    k_detect<<<1, 256>>>(ew);
    k_zero<<<(NN + 255) / 256, 256>>>();
    k_deg<<<(NE / 4 + 255) / 256, 256>>>(e32, e64);
    k_scanA<<<NB_SCAN, 1024>>>();
    k_scanB<<<1, 32>>>();
    k_scanC<<<NB_SCAN, 1024>>>();
    k_scatter<<<(NE / 4 + 255) / 256, 256>>>(e32, e64);

    k_cvtx<<<(NN * 32 + 255) / 256, 256>>>(x);                   // x -> hi/lo
    k_cvtw<<<(128 * 256 + 128 * 128 + 255) / 256, 256>>>(W1l, W1r, W2l, W2r);

    k_agg128<<<(NN * 32 + 255) / 256, 256>>>(x);                 // agg1 -> hi/lo
    k_gemm1<<<(NN + 127) / 128, 256>>>(b1);                      // h -> hi/lo
    k_gemm2<<<(NN + 127) / 128, 256>>>();                        // pr fp32
    k_agg64f<<<(NN * 32 + 255) / 256, 256>>>(b2, out);           // out (fused)
}

// round 11
// speedup vs baseline: 1.0080x; 1.0080x over previous
#include <cuda_runtime.h>
#include <cuda_bf16.h>
#include <cstdint>

#define NN 50000
#define NE 1600000
#define DIM 128
#define DOUT 64
#define NB_SCAN 49   // ceil(50000/1024)
#define APITCH 40    // bf16 pitch: 80B rows -> ldmatrix bank-conflict-free

// ---------------- scratch (device globals; no allocations allowed) ----------
__device__ int   g_is32;                     // 1 if edge_index is int32
__device__ int   g_deg[NN];
__device__ int   g_off[NN];
__device__ int   g_cur[NN];
__device__ int   g_bsum[64];
__device__ int   g_csr[NE];
// bf16 hi/lo planes (split-precision operands)
__device__ __align__(16) __nv_bfloat16 g_xh[(size_t)NN * DIM];
__device__ __align__(16) __nv_bfloat16 g_xl[(size_t)NN * DIM];
__device__ __align__(16) __nv_bfloat16 g_a1h[(size_t)NN * DIM];
__device__ __align__(16) __nv_bfloat16 g_a1l[(size_t)NN * DIM];
__device__ __align__(16) __nv_bfloat16 g_hh[(size_t)NN * DIM];
__device__ __align__(16) __nv_bfloat16 g_hl[(size_t)NN * DIM];
__device__ __align__(16) __nv_bfloat16 g_w1h[256 * 128];   // [n=128][k=256] transposed
__device__ __align__(16) __nv_bfloat16 g_w1l[256 * 128];
__device__ __align__(16) __nv_bfloat16 g_w2h[128 * 128];   // [n=128][k=128] transposed
__device__ __align__(16) __nv_bfloat16 g_w2l[128 * 128];
__device__ __align__(16) float g_pr[(size_t)NN * DIM];     // [h@W2l | h@W2r] fp32

// ---------------- mma / ldmatrix helpers ------------------------------------
__device__ __forceinline__ void mma16816(float* d, const unsigned* a,
                                         unsigned b0, unsigned b1) {
    asm("mma.sync.aligned.m16n8k16.row.col.f32.bf16.bf16.f32 "
        "{%0,%1,%2,%3}, {%4,%5,%6,%7}, {%8,%9}, {%0,%1,%2,%3};"
        : "+f"(d[0]), "+f"(d[1]), "+f"(d[2]), "+f"(d[3])
        : "r"(a[0]), "r"(a[1]), "r"(a[2]), "r"(a[3]), "r"(b0), "r"(b1));
}

__device__ __forceinline__ void ldm_x4(unsigned* r, const __nv_bfloat16* p) {
    unsigned addr = (unsigned)__cvta_generic_to_shared(p);
    asm volatile("ldmatrix.sync.aligned.m8n8.x4.shared.b16 {%0,%1,%2,%3}, [%4];"
                 : "=r"(r[0]), "=r"(r[1]), "=r"(r[2]), "=r"(r[3]) : "r"(addr));
}

__device__ __forceinline__ void split2(float f, __nv_bfloat16& h, __nv_bfloat16& l) {
    h = __float2bfloat16_rn(f);
    l = __float2bfloat16_rn(f - __bfloat162float(h));
}

// ---------------- one-time operand conversion --------------------------------
__global__ void k_cvtx(const float* __restrict__ x) {
    int i = blockIdx.x * blockDim.x + threadIdx.x;   // float4 index
    if (i >= NN * 32) return;
    float4 v = ((const float4*)x)[i];
    __nv_bfloat16 h0, l0, h1, l1, h2, l2, h3, l3;
    split2(v.x, h0, l0); split2(v.y, h1, l1);
    split2(v.z, h2, l2); split2(v.w, h3, l3);
    ((__nv_bfloat162*)g_xh)[i * 2]     = __nv_bfloat162{h0, h1};
    ((__nv_bfloat162*)g_xh)[i * 2 + 1] = __nv_bfloat162{h2, h3};
    ((__nv_bfloat162*)g_xl)[i * 2]     = __nv_bfloat162{l0, l1};
    ((__nv_bfloat162*)g_xl)[i * 2 + 1] = __nv_bfloat162{l2, l3};
}

// weights -> transposed hi/lo planes: g_w1 [n=128][k=256], g_w2 [n=128][k=128]
__global__ void k_cvtw(const float* __restrict__ W1l, const float* __restrict__ W1r,
                       const float* __restrict__ W2l, const float* __restrict__ W2r) {
    int i = blockIdx.x * blockDim.x + threadIdx.x;
    if (i < 128 * 256) {                 // W1: i = n*256 + k
        int n = i >> 8, k = i & 255;
        float v = (k < 128) ? W1l[(size_t)k * 128 + n]
                            : W1r[(size_t)(k - 128) * 128 + n];
        split2(v, g_w1h[i], g_w1l[i]);
    } else if (i < 128 * 256 + 128 * 128) {
        int j = i - 128 * 256;           // W2: j = n*128 + k
        int n = j >> 7, k = j & 127;
        float v = (n < 64) ? W2l[(size_t)k * 64 + n]
                           : W2r[(size_t)k * 64 + (n - 64)];
        split2(v, g_w2h[j], g_w2l[j]);
    }
}

// ---------------- dtype detection -------------------------------------------
__global__ void k_detect(const unsigned* __restrict__ w) {
    if (threadIdx.x == 0) g_is32 = 0;
    __syncthreads();
    int found = 0;
    for (int i = threadIdx.x; i < 1024; i += blockDim.x)
        if (w[2 * i + 1] != 0u) found = 1;
    if (found) atomicOr(&g_is32, 1);
}

// ---------------- CSR construction ------------------------------------------
__global__ void k_zero() {
    int i = blockIdx.x * blockDim.x + threadIdx.x;
    if (i < NN) g_deg[i] = 0;
}

__global__ void k_deg(const int* __restrict__ e32,
                      const long long* __restrict__ e64) {
    int base = (blockIdx.x * blockDim.x + threadIdx.x) * 4;
    if (base >= NE) return;
    int d0, d1, d2, d3;
    if (g_is32) {
        int4 v = *(const int4*)(e32 + NE + base);
        d0 = v.x; d1 = v.y; d2 = v.z; d3 = v.w;
    } else {
        longlong2 v0 = *(const longlong2*)(e64 + NE + base);
        longlong2 v1 = *(const longlong2*)(e64 + NE + base + 2);
        d0 = (int)v0.x; d1 = (int)v0.y; d2 = (int)v1.x; d3 = (int)v1.y;
    }
    if ((unsigned)d0 < NN) atomicAdd(&g_deg[d0], 1);
    if ((unsigned)d1 < NN) atomicAdd(&g_deg[d1], 1);
    if ((unsigned)d2 < NN) atomicAdd(&g_deg[d2], 1);
    if ((unsigned)d3 < NN) atomicAdd(&g_deg[d3], 1);
}

__global__ void k_scanA() {
    __shared__ int wsum[32];
    int i = blockIdx.x * 1024 + threadIdx.x;
    int v = (i < NN) ? g_deg[i] : 0;
    int lane = threadIdx.x & 31, wid = threadIdx.x >> 5;
    int s = v;
#pragma unroll
    for (int o = 1; o < 32; o <<= 1) {
        int t = __shfl_up_sync(0xffffffffu, s, o);
        if (lane >= o) s += t;
    }
    if (lane == 31) wsum[wid] = s;
    __syncthreads();
    if (wid == 0) {
        int ws = wsum[lane];
#pragma unroll
        for (int o = 1; o < 32; o <<= 1) {
            int t = __shfl_up_sync(0xffffffffu, ws, o);
            if (lane >= o) ws += t;
        }
        wsum[lane] = ws;
    }
    __syncthreads();
    int base = wid ? wsum[wid - 1] : 0;
    if (i < NN) g_off[i] = base + s - v;
    if (threadIdx.x == 0) g_bsum[blockIdx.x] = wsum[31];
}

__global__ void k_scanB() {
    if (threadIdx.x == 0 && blockIdx.x == 0) {
        int acc = 0;
        for (int b = 0; b < NB_SCAN; b++) { int t = g_bsum[b]; g_bsum[b] = acc; acc += t; }
    }
}

__global__ void k_scanC() {
    int i = blockIdx.x * 1024 + threadIdx.x;
    if (i < NN) {
        int o = g_off[i] + g_bsum[blockIdx.x];
        g_off[i] = o;
        g_cur[i] = o;
    }
}

__global__ void k_scatter(const int* __restrict__ e32,
                          const long long* __restrict__ e64) {
    int base = (blockIdx.x * blockDim.x + threadIdx.x) * 4;
    if (base >= NE) return;
    int s0, s1, s2, s3, d0, d1, d2, d3;
    if (g_is32) {
        int4 sv = *(const int4*)(e32 + base);
        int4 dv = *(const int4*)(e32 + NE + base);
        s0 = sv.x; s1 = sv.y; s2 = sv.z; s3 = sv.w;
        d0 = dv.x; d1 = dv.y; d2 = dv.z; d3 = dv.w;
    } else {
        longlong2 sa = *(const longlong2*)(e64 + base);
        longlong2 sb = *(const longlong2*)(e64 + base + 2);
        longlong2 da = *(const longlong2*)(e64 + NE + base);
        longlong2 db = *(const longlong2*)(e64 + NE + base + 2);
        s0 = (int)sa.x; s1 = (int)sa.y; s2 = (int)sb.x; s3 = (int)sb.y;
        d0 = (int)da.x; d1 = (int)da.y; d2 = (int)db.x; d3 = (int)db.y;
    }
    if ((unsigned)d0 < NN) g_csr[atomicAdd(&g_cur[d0], 1)] = ((unsigned)s0 < NN) ? s0 : 0;
    if ((unsigned)d1 < NN) g_csr[atomicAdd(&g_cur[d1], 1)] = ((unsigned)s1 < NN) ? s1 : 0;
    if ((unsigned)d2 < NN) g_csr[atomicAdd(&g_cur[d2], 1)] = ((unsigned)s2 < NN) ? s2 : 0;
    if ((unsigned)d3 < NN) g_csr[atomicAdd(&g_cur[d3], 1)] = ((unsigned)s3 < NN) ? s3 : 0;
}

// ---------------- aggregation (warp per node, CSR gather) -------------------
// mean-aggregate x -> hi/lo bf16 planes g_a1h/g_a1l
__global__ void k_agg128(const float* __restrict__ src) {
    int w = (blockIdx.x * blockDim.x + threadIdx.x) >> 5;
    if (w >= NN) return;
    int lane = threadIdx.x & 31;
    int start = g_off[w];
    int d = g_deg[w];
    const float4* sv = (const float4*)src;
    float4 a0 = make_float4(0.f, 0.f, 0.f, 0.f);
    float4 a1 = make_float4(0.f, 0.f, 0.f, 0.f);
    for (int j = 0; j < d; j += 32) {
        int m = min(32, d - j);
        int sidx = (j + lane < d) ? g_csr[start + j + lane] : 0;
        int jj = 0;
        for (; jj + 2 <= m; jj += 2) {
            int s0 = __shfl_sync(0xffffffffu, sidx, jj);
            int s1 = __shfl_sync(0xffffffffu, sidx, jj + 1);
            float4 v0 = sv[(size_t)s0 * 32 + lane];
            float4 v1 = sv[(size_t)s1 * 32 + lane];
            a0.x += v0.x; a0.y += v0.y; a0.z += v0.z; a0.w += v0.w;
            a1.x += v1.x; a1.y += v1.y; a1.z += v1.z; a1.w += v1.w;
        }
        if (jj < m) {
            int s0 = __shfl_sync(0xffffffffu, sidx, jj);
            float4 v0 = sv[(size_t)s0 * 32 + lane];
            a0.x += v0.x; a0.y += v0.y; a0.z += v0.z; a0.w += v0.w;
        }
    }
    float inv = 1.0f / (float)max(d, 1);
    float r0 = (a0.x + a1.x) * inv;
    float r1 = (a0.y + a1.y) * inv;
    float r2 = (a0.z + a1.z) * inv;
    float r3 = (a0.w + a1.w) * inv;
    __nv_bfloat16 h0, l0, h1, l1, h2, l2, h3, l3;
    split2(r0, h0, l0); split2(r1, h1, l1);
    split2(r2, h2, l2); split2(r3, h3, l3);
    size_t p = (size_t)w * 64 + lane * 2;        // __nv_bfloat162 index
    ((__nv_bfloat162*)g_a1h)[p]     = __nv_bfloat162{h0, h1};
    ((__nv_bfloat162*)g_a1h)[p + 1] = __nv_bfloat162{h2, h3};
    ((__nv_bfloat162*)g_a1l)[p]     = __nv_bfloat162{l0, l1};
    ((__nv_bfloat162*)g_a1l)[p + 1] = __nv_bfloat162{l2, l3};
}

// aggregate first 64 cols of g_pr (h@W2_l) + self term + bias -> out
__global__ void k_agg64f(const float* __restrict__ b2, float* __restrict__ out) {
    int w = (blockIdx.x * blockDim.x + threadIdx.x) >> 5;
    if (w >= NN) return;
    int lane = threadIdx.x & 31;
    int start = g_off[w];
    int d = g_deg[w];
    const float2* sv = (const float2*)g_pr;
    float2 a0 = make_float2(0.f, 0.f);
    float2 a1 = make_float2(0.f, 0.f);
    for (int j = 0; j < d; j += 32) {
        int m = min(32, d - j);
        int sidx = (j + lane < d) ? g_csr[start + j + lane] : 0;
        int jj = 0;
        for (; jj + 2 <= m; jj += 2) {
            int s0 = __shfl_sync(0xffffffffu, sidx, jj);
            int s1 = __shfl_sync(0xffffffffu, sidx, jj + 1);
            float2 v0 = sv[(size_t)s0 * 64 + lane];
            float2 v1 = sv[(size_t)s1 * 64 + lane];
            a0.x += v0.x; a0.y += v0.y;
            a1.x += v1.x; a1.y += v1.y;
        }
        if (jj < m) {
            int s0 = __shfl_sync(0xffffffffu, sidx, jj);
            float2 v0 = sv[(size_t)s0 * 64 + lane];
            a0.x += v0.x; a0.y += v0.y;
        }
    }
    float inv = 1.0f / (float)max(d, 1);
    float2 selfr = sv[(size_t)w * 64 + 32 + lane];
    float2 bb = ((const float2*)b2)[lane];
    float2 o;
    o.x = (a0.x + a1.x) * inv + selfr.x + bb.x;
    o.y = (a0.y + a1.y) * inv + selfr.y + bb.y;
    ((float2*)out)[(size_t)w * 32 + lane] = o;
}

// ---------------- GEMM 1 (bf16x3 TC, preconverted operands) ------------------
// h(hi/lo) = relu([agg1|x] @ [W1_l;W1_r] + b1); M=NN, N=128, K=256.
__global__ __launch_bounds__(256) void k_gemm1(const float* __restrict__ bias) {
    __shared__ __nv_bfloat16 Ah[128][APITCH], Al[128][APITCH];
    __shared__ __nv_bfloat16 Bh[128][APITCH], Bl[128][APITCH];  // BT: [n][k]
    const int tid = threadIdx.x, lane = tid & 31, wid = tid >> 5;
    const int wm = (wid & 1) * 64, wn = (wid >> 1) * 32;
    const int bm = blockIdx.x * 128;
    float acc[4][4][4];
#pragma unroll
    for (int mt = 0; mt < 4; mt++)
#pragma unroll
        for (int nt = 0; nt < 4; nt++)
#pragma unroll
            for (int q = 0; q < 4; q++) acc[mt][nt][q] = 0.f;

    for (int kc = 0; kc < 256; kc += 32) {
        // stage A: 128 rows x 32 k, hi/lo bf16 copies (8 bf16 per uint4)
#pragma unroll
        for (int i = 0; i < 2; i++) {
            int f = tid + 256 * i;            // 0..511
            int r = f >> 2, c8 = (f & 3) * 8;
            int row = bm + r, k = kc + c8;
            uint4 vh = make_uint4(0, 0, 0, 0), vl = make_uint4(0, 0, 0, 0);
            if (row < NN) {
                size_t idx = (k < 128) ? ((size_t)row * 128 + k)
                                       : ((size_t)row * 128 + (k - 128));
                const __nv_bfloat16* ph = (k < 128) ? g_a1h : g_xh;
                const __nv_bfloat16* pl = (k < 128) ? g_a1l : g_xl;
                vh = *(const uint4*)(ph + idx);
                vl = *(const uint4*)(pl + idx);
            }
            *(uint4*)&Ah[r][c8] = vh;
            *(uint4*)&Al[r][c8] = vl;
        }
        // stage B: [n][k] planes, straight copy
#pragma unroll
        for (int i = 0; i < 2; i++) {
            int f = tid + 256 * i;
            int n = f >> 2, c8 = (f & 3) * 8;
            *(uint4*)&Bh[n][c8] = *(const uint4*)(g_w1h + (size_t)n * 256 + kc + c8);
            *(uint4*)&Bl[n][c8] = *(const uint4*)(g_w1l + (size_t)n * 256 + kc + c8);
        }
        __syncthreads();
#pragma unroll
        for (int k16 = 0; k16 < 32; k16 += 16) {
            unsigned ah[4][4], al[4][4];
            int arow = wm + (lane & 15);
            int acol = k16 + ((lane >> 4) << 3);
#pragma unroll
            for (int mt = 0; mt < 4; mt++) {
                ldm_x4(ah[mt], &Ah[arow + mt * 16][acol]);
                ldm_x4(al[mt], &Al[arow + mt * 16][acol]);
            }
#pragma unroll
            for (int nt = 0; nt < 4; nt++) {
                int bn = wn + nt * 8 + (lane >> 2);
                int bk = k16 + 2 * (lane & 3);
                unsigned bh0 = *(const unsigned*)&Bh[bn][bk];
                unsigned bh1 = *(const unsigned*)&Bh[bn][bk + 8];
                unsigned bl0 = *(const unsigned*)&Bl[bn][bk];
                unsigned bl1 = *(const unsigned*)&Bl[bn][bk + 8];
#pragma unroll
                for (int mt = 0; mt < 4; mt++) {
                    mma16816(acc[mt][nt], ah[mt], bh0, bh1);
                    mma16816(acc[mt][nt], ah[mt], bl0, bl1);
                    mma16816(acc[mt][nt], al[mt], bh0, bh1);
                }
            }
        }
        __syncthreads();
    }
    // epilogue: bias + relu -> hi/lo planes
#pragma unroll
    for (int mt = 0; mt < 4; mt++) {
#pragma unroll
        for (int nt = 0; nt < 4; nt++) {
            int col = wn + nt * 8 + 2 * (lane & 3);
            float bv0 = bias[col], bv1 = bias[col + 1];
            int row0 = bm + wm + mt * 16 + (lane >> 2);
            if (row0 < NN) {
                float o0 = fmaxf(acc[mt][nt][0] + bv0, 0.f);
                float o1 = fmaxf(acc[mt][nt][1] + bv1, 0.f);
                __nv_bfloat16 h0, l0, h1, l1;
                split2(o0, h0, l0); split2(o1, h1, l1);
                *(__nv_bfloat162*)&g_hh[(size_t)row0 * 128 + col] = __nv_bfloat162{h0, h1};
                *(__nv_bfloat162*)&g_hl[(size_t)row0 * 128 + col] = __nv_bfloat162{l0, l1};
            }
            int row1 = row0 + 8;
            if (row1 < NN) {
                float o0 = fmaxf(acc[mt][nt][2] + bv0, 0.f);
                float o1 = fmaxf(acc[mt][nt][3] + bv1, 0.f);
                __nv_bfloat16 h0, l0, h1, l1;
                split2(o0, h0, l0); split2(o1, h1, l1);
                *(__nv_bfloat162*)&g_hh[(size_t)row1 * 128 + col] = __nv_bfloat162{h0, h1};
                *(__nv_bfloat162*)&g_hl[(size_t)row1 * 128 + col] = __nv_bfloat162{l0, l1};
            }
        }
    }
}

// ---------------- GEMM 2 (bf16x3 TC, preconverted operands) ------------------
// g_pr = h @ [W2_l | W2_r]; M=NN, N=128, K=128.
__global__ __launch_bounds__(256) void k_gemm2() {
    __shared__ __nv_bfloat16 Ah[128][APITCH], Al[128][APITCH];
    __shared__ __nv_bfloat16 Bh[128][APITCH], Bl[128][APITCH];
    const int tid = threadIdx.x, lane = tid & 31, wid = tid >> 5;
    const int wm = (wid & 1) * 64, wn = (wid >> 1) * 32;
    const int bm = blockIdx.x * 128;
    float acc[4][4][4];
#pragma unroll
    for (int mt = 0; mt < 4; mt++)
#pragma unroll
        for (int nt = 0; nt < 4; nt++)
#pragma unroll
            for (int q = 0; q < 4; q++) acc[mt][nt][q] = 0.f;

    for (int kc = 0; kc < 128; kc += 32) {
#pragma unroll
        for (int i = 0; i < 2; i++) {
            int f = tid + 256 * i;
            int r = f >> 2, c8 = (f & 3) * 8;
            int row = bm + r, k = kc + c8;
            uint4 vh = make_uint4(0, 0, 0, 0), vl = make_uint4(0, 0, 0, 0);
            if (row < NN) {
                vh = *(const uint4*)(g_hh + (size_t)row * 128 + k);
                vl = *(const uint4*)(g_hl + (size_t)row * 128 + k);
            }
            *(uint4*)&Ah[r][c8] = vh;
            *(uint4*)&Al[r][c8] = vl;
        }
#pragma unroll
        for (int i = 0; i < 2; i++) {
            int f = tid + 256 * i;
            int n = f >> 2, c8 = (f & 3) * 8;
            *(uint4*)&Bh[n][c8] = *(const uint4*)(g_w2h + (size_t)n * 128 + kc + c8);
            *(uint4*)&Bl[n][c8] = *(const uint4*)(g_w2l + (size_t)n * 128 + kc + c8);
        }
        __syncthreads();
#pragma unroll
        for (int k16 = 0; k16 < 32; k16 += 16) {
            unsigned ah[4][4], al[4][4];
            int arow = wm + (lane & 15);
            int acol = k16 + ((lane >> 4) << 3);
#pragma unroll
            for (int mt = 0; mt < 4; mt++) {
                ldm_x4(ah[mt], &Ah[arow + mt * 16][acol]);
                ldm_x4(al[mt], &Al[arow + mt * 16][acol]);
            }
#pragma unroll
            for (int nt = 0; nt < 4; nt++) {
                int bn = wn + nt * 8 + (lane >> 2);
                int bk = k16 + 2 * (lane & 3);
                unsigned bh0 = *(const unsigned*)&Bh[bn][bk];
                unsigned bh1 = *(const unsigned*)&Bh[bn][bk + 8];
                unsigned bl0 = *(const unsigned*)&Bl[bn][bk];
                unsigned bl1 = *(const unsigned*)&Bl[bn][bk + 8];
#pragma unroll
                for (int mt = 0; mt < 4; mt++) {
                    mma16816(acc[mt][nt], ah[mt], bh0, bh1);
                    mma16816(acc[mt][nt], ah[mt], bl0, bl1);
                    mma16816(acc[mt][nt], al[mt], bh0, bh1);
                }
            }
        }
        __syncthreads();
    }
#pragma unroll
    for (int mt = 0; mt < 4; mt++) {
#pragma unroll
        for (int nt = 0; nt < 4; nt++) {
            int col = wn + nt * 8 + 2 * (lane & 3);
            int row0 = bm + wm + mt * 16 + (lane >> 2);
            if (row0 < NN) {
                float2 o = make_float2(acc[mt][nt][0], acc[mt][nt][1]);
                *(float2*)&g_pr[(size_t)row0 * 128 + col] = o;
            }
            int row1 = row0 + 8;
            if (row1 < NN) {
                float2 o = make_float2(acc[mt][nt][2], acc[mt][nt][3]);
                *(float2*)&g_pr[(size_t)row1 * 128 + col] = o;
            }
        }
    }
}

// ---------------- launch ----------------------------------------------------
extern "C" void kernel_launch(void* const* d_in, const int* in_sizes, int n_in,
                              void* d_out, int out_size) {
    const float*     x   = (const float*)d_in[0];
    const int*       e32 = (const int*)d_in[1];
    const long long* e64 = (const long long*)d_in[1];
    const unsigned*  ew  = (const unsigned*)d_in[1];
    const float*     W1l = (const float*)d_in[2];
    const float*     W1r = (const float*)d_in[3];
    const float*     b1  = (const float*)d_in[4];
    const float*     W2l = (const float*)d_in[5];
    const float*     W2r = (const float*)d_in[6];
    const float*     b2  = (const float*)d_in[7];
    float*           out = (float*)d_out;

    k_detect<<<1, 256>>>(ew);
    k_zero<<<(NN + 255) / 256, 256>>>();
    k_deg<<<(NE / 4 + 255) / 256, 256>>>(e32, e64);
    k_scanA<<<NB_SCAN, 1024>>>();
    k_scanB<<<1, 32>>>();
    k_scanC<<<NB_SCAN, 1024>>>();
    k_scatter<<<(NE / 4 + 255) / 256, 256>>>(e32, e64);

    k_cvtx<<<(NN * 32 + 255) / 256, 256>>>(x);                   // x -> hi/lo
    k_cvtw<<<(128 * 256 + 128 * 128 + 255) / 256, 256>>>(W1l, W1r, W2l, W2r);

    k_agg128<<<(NN * 32 + 255) / 256, 256>>>(x);                 // agg1 -> hi/lo
    k_gemm1<<<(NN + 127) / 128, 256>>>(b1);                      // h -> hi/lo
    k_gemm2<<<(NN + 127) / 128, 256>>>();                        // pr fp32
    k_agg64f<<<(NN * 32 + 255) / 256, 256>>>(b2, out);           // out (fused)
}

// round 12
// speedup vs baseline: 1.0092x; 1.0011x over previous
#include <cuda_runtime.h>
#include <cuda_bf16.h>
#include <cstdint>

#define NN 50000
#define NE 1600000
#define DIM 128
#define DOUT 64
#define NB_SCAN 49   // ceil(50000/1024)
#define APITCH 40    // bf16 pitch: 80B rows -> ldmatrix bank-conflict-free

// ---------------- scratch (device globals; no allocations allowed) ----------
__device__ int   g_is32;                     // 1 if edge_index is int32
__device__ int   g_deg[NN];
__device__ int   g_off[NN];
__device__ int   g_cur[NN];
__device__ int   g_bsum[64];
__device__ int   g_csr[NE];
// bf16 hi/lo planes (split-precision operands)
__device__ __align__(16) __nv_bfloat16 g_xh[(size_t)NN * DIM];
__device__ __align__(16) __nv_bfloat16 g_xl[(size_t)NN * DIM];
__device__ __align__(16) __nv_bfloat16 g_a1h[(size_t)NN * DIM];
__device__ __align__(16) __nv_bfloat16 g_a1l[(size_t)NN * DIM];
__device__ __align__(16) __nv_bfloat16 g_hh[(size_t)NN * DIM];
__device__ __align__(16) __nv_bfloat16 g_hl[(size_t)NN * DIM];
__device__ __align__(16) __nv_bfloat16 g_w1h[256 * 128];   // [n=128][k=256] transposed
__device__ __align__(16) __nv_bfloat16 g_w1l[256 * 128];
__device__ __align__(16) __nv_bfloat16 g_w2h[128 * 128];   // [n=128][k=128] transposed
__device__ __align__(16) __nv_bfloat16 g_w2l[128 * 128];
__device__ __align__(16) float g_pr[(size_t)NN * DIM];     // [h@W2l | h@W2r] fp32

// ---------------- mma / ldmatrix helpers ------------------------------------
__device__ __forceinline__ void mma16816(float* d, const unsigned* a,
                                         unsigned b0, unsigned b1) {
    asm("mma.sync.aligned.m16n8k16.row.col.f32.bf16.bf16.f32 "
        "{%0,%1,%2,%3}, {%4,%5,%6,%7}, {%8,%9}, {%0,%1,%2,%3};"
        : "+f"(d[0]), "+f"(d[1]), "+f"(d[2]), "+f"(d[3])
        : "r"(a[0]), "r"(a[1]), "r"(a[2]), "r"(a[3]), "r"(b0), "r"(b1));
}

__device__ __forceinline__ void ldm_x4(unsigned* r, const __nv_bfloat16* p) {
    unsigned addr = (unsigned)__cvta_generic_to_shared(p);
    asm volatile("ldmatrix.sync.aligned.m8n8.x4.shared.b16 {%0,%1,%2,%3}, [%4];"
                 : "=r"(r[0]), "=r"(r[1]), "=r"(r[2]), "=r"(r[3]) : "r"(addr));
}

__device__ __forceinline__ void split2(float f, __nv_bfloat16& h, __nv_bfloat16& l) {
    h = __float2bfloat16_rn(f);
    l = __float2bfloat16_rn(f - __bfloat162float(h));
}

// ---------------- one-time operand conversion --------------------------------
__global__ void k_cvtx(const float* __restrict__ x) {
    int i = blockIdx.x * blockDim.x + threadIdx.x;   // float4 index
    if (i >= NN * 32) return;
    float4 v = ((const float4*)x)[i];
    __nv_bfloat16 h0, l0, h1, l1, h2, l2, h3, l3;
    split2(v.x, h0, l0); split2(v.y, h1, l1);
    split2(v.z, h2, l2); split2(v.w, h3, l3);
    ((__nv_bfloat162*)g_xh)[i * 2]     = __nv_bfloat162{h0, h1};
    ((__nv_bfloat162*)g_xh)[i * 2 + 1] = __nv_bfloat162{h2, h3};
    ((__nv_bfloat162*)g_xl)[i * 2]     = __nv_bfloat162{l0, l1};
    ((__nv_bfloat162*)g_xl)[i * 2 + 1] = __nv_bfloat162{l2, l3};
}

// weights -> transposed hi/lo planes: g_w1 [n=128][k=256], g_w2 [n=128][k=128]
__global__ void k_cvtw(const float* __restrict__ W1l, const float* __restrict__ W1r,
                       const float* __restrict__ W2l, const float* __restrict__ W2r) {
    int i = blockIdx.x * blockDim.x + threadIdx.x;
    if (i < 128 * 256) {                 // W1: i = n*256 + k
        int n = i >> 8, k = i & 255;
        float v = (k < 128) ? W1l[(size_t)k * 128 + n]
                            : W1r[(size_t)(k - 128) * 128 + n];
        split2(v, g_w1h[i], g_w1l[i]);
    } else if (i < 128 * 256 + 128 * 128) {
        int j = i - 128 * 256;           // W2: j = n*128 + k
        int n = j >> 7, k = j & 127;
        float v = (n < 64) ? W2l[(size_t)k * 64 + n]
                           : W2r[(size_t)k * 64 + (n - 64)];
        split2(v, g_w2h[j], g_w2l[j]);
    }
}

// ---------------- dtype detection -------------------------------------------
__global__ void k_detect(const unsigned* __restrict__ w) {
    if (threadIdx.x == 0) g_is32 = 0;
    __syncthreads();
    int found = 0;
    for (int i = threadIdx.x; i < 1024; i += blockDim.x)
        if (w[2 * i + 1] != 0u) found = 1;
    if (found) atomicOr(&g_is32, 1);
}

// ---------------- CSR construction ------------------------------------------
__global__ void k_zero() {
    int i = blockIdx.x * blockDim.x + threadIdx.x;
    if (i < NN) g_deg[i] = 0;
}

__global__ void k_deg(const int* __restrict__ e32,
                      const long long* __restrict__ e64) {
    int base = (blockIdx.x * blockDim.x + threadIdx.x) * 4;
    if (base >= NE) return;
    int d0, d1, d2, d3;
    if (g_is32) {
        int4 v = *(const int4*)(e32 + NE + base);
        d0 = v.x; d1 = v.y; d2 = v.z; d3 = v.w;
    } else {
        longlong2 v0 = *(const longlong2*)(e64 + NE + base);
        longlong2 v1 = *(const longlong2*)(e64 + NE + base + 2);
        d0 = (int)v0.x; d1 = (int)v0.y; d2 = (int)v1.x; d3 = (int)v1.y;
    }
    if ((unsigned)d0 < NN) atomicAdd(&g_deg[d0], 1);
    if ((unsigned)d1 < NN) atomicAdd(&g_deg[d1], 1);
    if ((unsigned)d2 < NN) atomicAdd(&g_deg[d2], 1);
    if ((unsigned)d3 < NN) atomicAdd(&g_deg[d3], 1);
}

__global__ void k_scanA() {
    __shared__ int wsum[32];
    int i = blockIdx.x * 1024 + threadIdx.x;
    int v = (i < NN) ? g_deg[i] : 0;
    int lane = threadIdx.x & 31, wid = threadIdx.x >> 5;
    int s = v;
#pragma unroll
    for (int o = 1; o < 32; o <<= 1) {
        int t = __shfl_up_sync(0xffffffffu, s, o);
        if (lane >= o) s += t;
    }
    if (lane == 31) wsum[wid] = s;
    __syncthreads();
    if (wid == 0) {
        int ws = wsum[lane];
#pragma unroll
        for (int o = 1; o < 32; o <<= 1) {
            int t = __shfl_up_sync(0xffffffffu, ws, o);
            if (lane >= o) ws += t;
        }
        wsum[lane] = ws;
    }
    __syncthreads();
    int base = wid ? wsum[wid - 1] : 0;
    if (i < NN) g_off[i] = base + s - v;
    if (threadIdx.x == 0) g_bsum[blockIdx.x] = wsum[31];
}

__global__ void k_scanB() {
    if (threadIdx.x == 0 && blockIdx.x == 0) {
        int acc = 0;
        for (int b = 0; b < NB_SCAN; b++) { int t = g_bsum[b]; g_bsum[b] = acc; acc += t; }
    }
}

__global__ void k_scanC() {
    int i = blockIdx.x * 1024 + threadIdx.x;
    if (i < NN) {
        int o = g_off[i] + g_bsum[blockIdx.x];
        g_off[i] = o;
        g_cur[i] = o;
    }
}

__global__ void k_scatter(const int* __restrict__ e32,
                          const long long* __restrict__ e64) {
    int base = (blockIdx.x * blockDim.x + threadIdx.x) * 4;
    if (base >= NE) return;
    int s0, s1, s2, s3, d0, d1, d2, d3;
    if (g_is32) {
        int4 sv = *(const int4*)(e32 + base);
        int4 dv = *(const int4*)(e32 + NE + base);
        s0 = sv.x; s1 = sv.y; s2 = sv.z; s3 = sv.w;
        d0 = dv.x; d1 = dv.y; d2 = dv.z; d3 = dv.w;
    } else {
        longlong2 sa = *(const longlong2*)(e64 + base);
        longlong2 sb = *(const longlong2*)(e64 + base + 2);
        longlong2 da = *(const longlong2*)(e64 + NE + base);
        longlong2 db = *(const longlong2*)(e64 + NE + base + 2);
        s0 = (int)sa.x; s1 = (int)sa.y; s2 = (int)sb.x; s3 = (int)sb.y;
        d0 = (int)da.x; d1 = (int)da.y; d2 = (int)db.x; d3 = (int)db.y;
    }
    if ((unsigned)d0 < NN) g_csr[atomicAdd(&g_cur[d0], 1)] = ((unsigned)s0 < NN) ? s0 : 0;
    if ((unsigned)d1 < NN) g_csr[atomicAdd(&g_cur[d1], 1)] = ((unsigned)s1 < NN) ? s1 : 0;
    if ((unsigned)d2 < NN) g_csr[atomicAdd(&g_cur[d2], 1)] = ((unsigned)s2 < NN) ? s2 : 0;
    if ((unsigned)d3 < NN) g_csr[atomicAdd(&g_cur[d3], 1)] = ((unsigned)s3 < NN) ? s3 : 0;
}

// ---------------- aggregation (warp per node, CSR gather) -------------------
// mean-aggregate x -> hi/lo bf16 planes g_a1h/g_a1l
__global__ void k_agg128(const float* __restrict__ src) {
    int w = (blockIdx.x * blockDim.x + threadIdx.x) >> 5;
    if (w >= NN) return;
    int lane = threadIdx.x & 31;
    int start = g_off[w];
    int d = g_deg[w];
    const float4* sv = (const float4*)src;
    float4 a0 = make_float4(0.f, 0.f, 0.f, 0.f);
    float4 a1 = make_float4(0.f, 0.f, 0.f, 0.f);
    for (int j = 0; j < d; j += 32) {
        int m = min(32, d - j);
        int sidx = (j + lane < d) ? g_csr[start + j + lane] : 0;
        int jj = 0;
        for (; jj + 2 <= m; jj += 2) {
            int s0 = __shfl_sync(0xffffffffu, sidx, jj);
            int s1 = __shfl_sync(0xffffffffu, sidx, jj + 1);
            float4 v0 = sv[(size_t)s0 * 32 + lane];
            float4 v1 = sv[(size_t)s1 * 32 + lane];
            a0.x += v0.x; a0.y += v0.y; a0.z += v0.z; a0.w += v0.w;
            a1.x += v1.x; a1.y += v1.y; a1.z += v1.z; a1.w += v1.w;
        }
        if (jj < m) {
            int s0 = __shfl_sync(0xffffffffu, sidx, jj);
            float4 v0 = sv[(size_t)s0 * 32 + lane];
            a0.x += v0.x; a0.y += v0.y; a0.z += v0.z; a0.w += v0.w;
        }
    }
    float inv = 1.0f / (float)max(d, 1);
    float r0 = (a0.x + a1.x) * inv;
    float r1 = (a0.y + a1.y) * inv;
    float r2 = (a0.z + a1.z) * inv;
    float r3 = (a0.w + a1.w) * inv;
    __nv_bfloat16 h0, l0, h1, l1, h2, l2, h3, l3;
    split2(r0, h0, l0); split2(r1, h1, l1);
    split2(r2, h2, l2); split2(r3, h3, l3);
    size_t p = (size_t)w * 64 + lane * 2;        // __nv_bfloat162 index
    ((__nv_bfloat162*)g_a1h)[p]     = __nv_bfloat162{h0, h1};
    ((__nv_bfloat162*)g_a1h)[p + 1] = __nv_bfloat162{h2, h3};
    ((__nv_bfloat162*)g_a1l)[p]     = __nv_bfloat162{l0, l1};
    ((__nv_bfloat162*)g_a1l)[p + 1] = __nv_bfloat162{l2, l3};
}

// aggregate first 64 cols of g_pr (h@W2_l) + self term + bias -> out
__global__ void k_agg64f(const float* __restrict__ b2, float* __restrict__ out) {
    int w = (blockIdx.x * blockDim.x + threadIdx.x) >> 5;
    if (w >= NN) return;
    int lane = threadIdx.x & 31;
    int start = g_off[w];
    int d = g_deg[w];
    const float2* sv = (const float2*)g_pr;
    float2 a0 = make_float2(0.f, 0.f);
    float2 a1 = make_float2(0.f, 0.f);
    for (int j = 0; j < d; j += 32) {
        int m = min(32, d - j);
        int sidx = (j + lane < d) ? g_csr[start + j + lane] : 0;
        int jj = 0;
        for (; jj + 2 <= m; jj += 2) {
            int s0 = __shfl_sync(0xffffffffu, sidx, jj);
            int s1 = __shfl_sync(0xffffffffu, sidx, jj + 1);
            float2 v0 = sv[(size_t)s0 * 64 + lane];
            float2 v1 = sv[(size_t)s1 * 64 + lane];
            a0.x += v0.x; a0.y += v0.y;
            a1.x += v1.x; a1.y += v1.y;
        }
        if (jj < m) {
            int s0 = __shfl_sync(0xffffffffu, sidx, jj);
            float2 v0 = sv[(size_t)s0 * 64 + lane];
            a0.x += v0.x; a0.y += v0.y;
        }
    }
    float inv = 1.0f / (float)max(d, 1);
    float2 selfr = sv[(size_t)w * 64 + 32 + lane];
    float2 bb = ((const float2*)b2)[lane];
    float2 o;
    o.x = (a0.x + a1.x) * inv + selfr.x + bb.x;
    o.y = (a0.y + a1.y) * inv + selfr.y + bb.y;
    ((float2*)out)[(size_t)w * 32 + lane] = o;
}

// ---------------- GEMM 1 (bf16x3 TC, preconverted operands) ------------------
// h(hi/lo) = relu([agg1|x] @ [W1_l;W1_r] + b1); M=NN, N=128, K=256.
__global__ __launch_bounds__(256) void k_gemm1(const float* __restrict__ bias) {
    __shared__ __nv_bfloat16 Ah[128][APITCH], Al[128][APITCH];
    __shared__ __nv_bfloat16 Bh[128][APITCH], Bl[128][APITCH];  // BT: [n][k]
    const int tid = threadIdx.x, lane = tid & 31, wid = tid >> 5;
    const int wm = (wid & 1) * 64, wn = (wid >> 1) * 32;
    const int bm = blockIdx.x * 128;
    float acc[4][4][4];
#pragma unroll
    for (int mt = 0; mt < 4; mt++)
#pragma unroll
        for (int nt = 0; nt < 4; nt++)
#pragma unroll
            for (int q = 0; q < 4; q++) acc[mt][nt][q] = 0.f;

    for (int kc = 0; kc < 256; kc += 32) {
        // stage A: 128 rows x 32 k, hi/lo bf16 copies (8 bf16 per uint4)
#pragma unroll
        for (int i = 0; i < 2; i++) {
            int f = tid + 256 * i;            // 0..511
            int r = f >> 2, c8 = (f & 3) * 8;
            int row = bm + r, k = kc + c8;
            uint4 vh = make_uint4(0, 0, 0, 0), vl = make_uint4(0, 0, 0, 0);
            if (row < NN) {
                size_t idx = (k < 128) ? ((size_t)row * 128 + k)
                                       : ((size_t)row * 128 + (k - 128));
                const __nv_bfloat16* ph = (k < 128) ? g_a1h : g_xh;
                const __nv_bfloat16* pl = (k < 128) ? g_a1l : g_xl;
                vh = *(const uint4*)(ph + idx);
                vl = *(const uint4*)(pl + idx);
            }
            *(uint4*)&Ah[r][c8] = vh;
            *(uint4*)&Al[r][c8] = vl;
        }
        // stage B: [n][k] planes, straight copy
#pragma unroll
        for (int i = 0; i < 2; i++) {
            int f = tid + 256 * i;
            int n = f >> 2, c8 = (f & 3) * 8;
            *(uint4*)&Bh[n][c8] = *(const uint4*)(g_w1h + (size_t)n * 256 + kc + c8);
            *(uint4*)&Bl[n][c8] = *(const uint4*)(g_w1l + (size_t)n * 256 + kc + c8);
        }
        __syncthreads();
#pragma unroll
        for (int k16 = 0; k16 < 32; k16 += 16) {
            unsigned ah[4][4], al[4][4];
            int arow = wm + (lane & 15);
            int acol = k16 + ((lane >> 4) << 3);
#pragma unroll
            for (int mt = 0; mt < 4; mt++) {
                ldm_x4(ah[mt], &Ah[arow + mt * 16][acol]);
                ldm_x4(al[mt], &Al[arow + mt * 16][acol]);
            }
#pragma unroll
            for (int nt = 0; nt < 4; nt++) {
                int bn = wn + nt * 8 + (lane >> 2);
                int bk = k16 + 2 * (lane & 3);
                unsigned bh0 = *(const unsigned*)&Bh[bn][bk];
                unsigned bh1 = *(const unsigned*)&Bh[bn][bk + 8];
                unsigned bl0 = *(const unsigned*)&Bl[bn][bk];
                unsigned bl1 = *(const unsigned*)&Bl[bn][bk + 8];
#pragma unroll
                for (int mt = 0; mt < 4; mt++) {
                    mma16816(acc[mt][nt], ah[mt], bh0, bh1);
                    mma16816(acc[mt][nt], ah[mt], bl0, bl1);
                    mma16816(acc[mt][nt], al[mt], bh0, bh1);
                }
            }
        }
        __syncthreads();
    }
    // epilogue: bias + relu -> hi/lo planes
#pragma unroll
    for (int mt = 0; mt < 4; mt++) {
#pragma unroll
        for (int nt = 0; nt < 4; nt++) {
            int col = wn + nt * 8 + 2 * (lane & 3);
            float bv0 = bias[col], bv1 = bias[col + 1];
            int row0 = bm + wm + mt * 16 + (lane >> 2);
            if (row0 < NN) {
                float o0 = fmaxf(acc[mt][nt][0] + bv0, 0.f);
                float o1 = fmaxf(acc[mt][nt][1] + bv1, 0.f);
                __nv_bfloat16 h0, l0, h1, l1;
                split2(o0, h0, l0); split2(o1, h1, l1);
                *(__nv_bfloat162*)&g_hh[(size_t)row0 * 128 + col] = __nv_bfloat162{h0, h1};
                *(__nv_bfloat162*)&g_hl[(size_t)row0 * 128 + col] = __nv_bfloat162{l0, l1};
            }
            int row1 = row0 + 8;
            if (row1 < NN) {
                float o0 = fmaxf(acc[mt][nt][2] + bv0, 0.f);
                float o1 = fmaxf(acc[mt][nt][3] + bv1, 0.f);
                __nv_bfloat16 h0, l0, h1, l1;
                split2(o0, h0, l0); split2(o1, h1, l1);
                *(__nv_bfloat162*)&g_hh[(size_t)row1 * 128 + col] = __nv_bfloat162{h0, h1};
                *(__nv_bfloat162*)&g_hl[(size_t)row1 * 128 + col] = __nv_bfloat162{l0, l1};
            }
        }
    }
}

// ---------------- GEMM 2 (bf16x3 TC, preconverted operands) ------------------
// g_pr = h @ [W2_l | W2_r]; M=NN, N=128, K=128.
__global__ __launch_bounds__(256) void k_gemm2() {
    __shared__ __nv_bfloat16 Ah[128][APITCH], Al[128][APITCH];
    __shared__ __nv_bfloat16 Bh[128][APITCH], Bl[128][APITCH];
    const int tid = threadIdx.x, lane = tid & 31, wid = tid >> 5;
    const int wm = (wid & 1) * 64, wn = (wid >> 1) * 32;
    const int bm = blockIdx.x * 128;
    float acc[4][4][4];
#pragma unroll
    for (int mt = 0; mt < 4; mt++)
#pragma unroll
        for (int nt = 0; nt < 4; nt++)
#pragma unroll
            for (int q = 0; q < 4; q++) acc[mt][nt][q] = 0.f;

    for (int kc = 0; kc < 128; kc += 32) {
#pragma unroll
        for (int i = 0; i < 2; i++) {
            int f = tid + 256 * i;
            int r = f >> 2, c8 = (f & 3) * 8;
            int row = bm + r, k = kc + c8;
            uint4 vh = make_uint4(0, 0, 0, 0), vl = make_uint4(0, 0, 0, 0);
            if (row < NN) {
                vh = *(const uint4*)(g_hh + (size_t)row * 128 + k);
                vl = *(const uint4*)(g_hl + (size_t)row * 128 + k);
            }
            *(uint4*)&Ah[r][c8] = vh;
            *(uint4*)&Al[r][c8] = vl;
        }
#pragma unroll
        for (int i = 0; i < 2; i++) {
            int f = tid + 256 * i;
            int n = f >> 2, c8 = (f & 3) * 8;
            *(uint4*)&Bh[n][c8] = *(const uint4*)(g_w2h + (size_t)n * 128 + kc + c8);
            *(uint4*)&Bl[n][c8] = *(const uint4*)(g_w2l + (size_t)n * 128 + kc + c8);
        }
        __syncthreads();
#pragma unroll
        for (int k16 = 0; k16 < 32; k16 += 16) {
            unsigned ah[4][4], al[4][4];
            int arow = wm + (lane & 15);
            int acol = k16 + ((lane >> 4) << 3);
#pragma unroll
            for (int mt = 0; mt < 4; mt++) {
                ldm_x4(ah[mt], &Ah[arow + mt * 16][acol]);
                ldm_x4(al[mt], &Al[arow + mt * 16][acol]);
            }
#pragma unroll
            for (int nt = 0; nt < 4; nt++) {
                int bn = wn + nt * 8 + (lane >> 2);
                int bk = k16 + 2 * (lane & 3);
                unsigned bh0 = *(const unsigned*)&Bh[bn][bk];
                unsigned bh1 = *(const unsigned*)&Bh[bn][bk + 8];
                unsigned bl0 = *(const unsigned*)&Bl[bn][bk];
                unsigned bl1 = *(const unsigned*)&Bl[bn][bk + 8];
#pragma unroll
                for (int mt = 0; mt < 4; mt++) {
                    mma16816(acc[mt][nt], ah[mt], bh0, bh1);
                    mma16816(acc[mt][nt], ah[mt], bl0, bl1);
                    mma16816(acc[mt][nt], al[mt], bh0, bh1);
                }
            }
        }
        __syncthreads();
    }
#pragma unroll
    for (int mt = 0; mt < 4; mt++) {
#pragma unroll
        for (int nt = 0; nt < 4; nt++) {
            int col = wn + nt * 8 + 2 * (lane & 3);
            int row0 = bm + wm + mt * 16 + (lane >> 2);
            if (row0 < NN) {
                float2 o = make_float2(acc[mt][nt][0], acc[mt][nt][1]);
                *(float2*)&g_pr[(size_t)row0 * 128 + col] = o;
            }
            int row1 = row0 + 8;
            if (row1 < NN) {
                float2 o = make_float2(acc[mt][nt][2], acc[mt][nt][3]);
                *(float2*)&g_pr[(size_t)row1 * 128 + col] = o;
            }
        }
    }
}

// ---------------- launch ----------------------------------------------------
extern "C" void kernel_launch(void* const* d_in, const int* in_sizes, int n_in,
                              void* d_out, int out_size) {
    const float*     x   = (const float*)d_in[0];
    const int*       e32 = (const int*)d_in[1];
    const long long* e64 = (const long long*)d_in[1];
    const unsigned*  ew  = (const unsigned*)d_in[1];
    const float*     W1l = (const float*)d_in[2];
    const float*     W1r = (const float*)d_in[3];
    const float*     b1  = (const float*)d_in[4];
    const float*     W2l = (const float*)d_in[5];
    const float*     W2r = (const float*)d_in[6];
    const float*     b2  = (const float*)d_in[7];
    float*           out = (float*)d_out;

    k_detect<<<1, 256>>>(ew);
    k_zero<<<(NN + 255) / 256, 256>>>();
    k_deg<<<(NE / 4 + 255) / 256, 256>>>(e32, e64);
    k_scanA<<<NB_SCAN, 1024>>>();
    k_scanB<<<1, 32>>>();
    k_scanC<<<NB_SCAN, 1024>>>();
    k_scatter<<<(NE / 4 + 255) / 256, 256>>>(e32, e64);

    k_cvtx<<<(NN * 32 + 255) / 256, 256>>>(x);                   // x -> hi/lo
    k_cvtw<<<(128 * 256 + 128 * 128 + 255) / 256, 256>>>(W1l, W1r, W2l, W2r);

    k_agg128<<<(NN * 32 + 255) / 256, 256>>>(x);                 // agg1 -> hi/lo
    k_gemm1<<<(NN + 127) / 128, 256>>>(b1);                      // h -> hi/lo
    k_gemm2<<<(NN + 127) / 128, 256>>>();                        // pr fp32
    k_agg64f<<<(NN * 32 + 255) / 256, 256>>>(b2, out);           // out (fused)
}